// round 7
// baseline (speedup 1.0000x reference)
#include <cuda_runtime.h>
#include <cuda_bf16.h>
#include <cstdint>

// PCEN, 10 smoother coefficients.
//   m[s,t] = (1-s)*m[s,t-1] + s*x[t],  m[s,0] = x[0]
//   out = (x*(EPS+m)^(-alpha) + delta)^r - delta^r
//
// R7: CPW=2 (R4 instruction economy) + 3 MUFU + 1 poly-ex2 (R5 pipe balance)
// + __launch_bounds__(128,11) forcing <=46 regs (~69% occupancy).
// a3/a128 recomputed per chunk to fit the register budget.

#define PCEN_EPS 1e-5f
#define NS 10
#define CPW 2
#define NPAIR (NS / CPW)
#define TT 2048
#define RPT 4
#define CHUNK (32 * RPT)
#define NCHUNK (TT / CHUNK)

__device__ __forceinline__ float fast_ex2(float v) {
    float r; asm("ex2.approx.ftz.f32 %0, %1;" : "=f"(r) : "f"(v)); return r;
}
__device__ __forceinline__ float fast_lg2(float v) {
    float r; asm("lg2.approx.ftz.f32 %0, %1;" : "=f"(r) : "f"(v)); return r;
}

// 2^v on FMA/ALU pipes (no MUFU). Valid for |v| < ~126.
__device__ __forceinline__ float poly_ex2(float v) {
    const float magic = 12582912.0f;           // 1.5 * 2^23
    float fl = v + magic;                      // RN -> integer in low mantissa
    int   iv = __float_as_int(fl);
    float t  = v - (fl - magic);               // t in [-0.5, 0.5]
    float u  = t * 0.6931471805599453f;
    float p  = fmaf(u, 8.3333333e-3f, 4.1666667e-2f);
    p = fmaf(p, u, 0.16666667f);
    p = fmaf(p, u, 0.5f);
    p = fmaf(p, u, 1.0f);
    p = fmaf(p, u, 1.0f);
    return __int_as_float(__float_as_int(p) + (iv << 23));
}

__global__ __launch_bounds__(128, 11) void pcen_kernel(
    const float* __restrict__ x,
    const float* __restrict__ s_log,
    const float* __restrict__ alpha_log,
    const float* __restrict__ delta_log,
    const float* __restrict__ r_log,
    float* __restrict__ out,
    int F, int BF)
{
    const int gwarp = (blockIdx.x * blockDim.x + threadIdx.x) >> 5;
    const int lane  = threadIdx.x & 31;
    if (gwarp >= BF * NPAIR) return;

    const int row  = gwarp / NPAIR;
    const int pair = gwarp % NPAIR;
    const int i0   = pair * CPW;

    const int b = row / F;
    const int f = row % F;

    const float alpha = __expf(alpha_log[f]);
    const float delta = __expf(delta_log[f]);
    const float r     = __expf(r_log[f]);
    const float delta_r = fast_ex2(r * fast_lg2(delta));

    const float4* __restrict__ xp4 = (const float4*)(x + (size_t)row * TT);
    float* __restrict__ op = out + (((size_t)b * NS + i0) * F + f) * (size_t)TT;
    const size_t s_stride = (size_t)F * TT;

    // persistent per-chain state: 10 regs per chain
    float sv[CPW], a1[CPW], a2[CPW], a4[CPW];
    float a8[CPW], a16[CPW], a32[CPW], a64[CPW];
    float a4lane[CPW], carry[CPW];

    const float x0 = ((const float*)xp4)[0];

    #pragma unroll
    for (int c = 0; c < CPW; c++) {
        const float s = __expf(s_log[i0 + c]);
        sv[c] = s;
        const float a = 1.0f - s;
        a1[c]  = a;
        a2[c]  = a * a;
        a4[c]  = a2[c] * a2[c];
        a8[c]  = a4[c] * a4[c];
        a16[c] = a8[c] * a8[c];
        a32[c] = a16[c] * a16[c];
        a64[c] = a32[c] * a32[c];
        float ap = 1.0f;                       // (a^4)^lane
        if (lane & 1)  ap *= a4[c];
        if (lane & 2)  ap *= a8[c];
        if (lane & 4)  ap *= a16[c];
        if (lane & 8)  ap *= a32[c];
        if (lane & 16) ap *= a64[c];
        a4lane[c] = ap;
        carry[c] = x0;   // m_{-1} = x0 -> m_0 = x0 (reference init)
    }

    for (int ch = 0; ch < NCHUNK; ch++) {
        const float4 xv = xp4[ch * 32 + lane];

        #pragma unroll
        for (int c = 0; c < CPW; c++) {
            const float s = sv[c];
            // local serial IIR (zero init)
            const float l0 = s * xv.x;
            const float l1 = fmaf(a1[c], l0, s * xv.y);
            const float l2 = fmaf(a1[c], l1, s * xv.z);
            const float l3 = fmaf(a1[c], l2, s * xv.w);

            // Kogge-Stone over lane aggregates (ratio a^4)
            float S = l3;
            float v;
            v = __shfl_up_sync(0xFFFFFFFFu, S, 1);  if (lane >= 1)  S = fmaf(a4[c],  v, S);
            v = __shfl_up_sync(0xFFFFFFFFu, S, 2);  if (lane >= 2)  S = fmaf(a8[c],  v, S);
            v = __shfl_up_sync(0xFFFFFFFFu, S, 4);  if (lane >= 4)  S = fmaf(a16[c], v, S);
            v = __shfl_up_sync(0xFFFFFFFFu, S, 8);  if (lane >= 8)  S = fmaf(a32[c], v, S);
            v = __shfl_up_sync(0xFFFFFFFFu, S, 16); if (lane >= 16) S = fmaf(a64[c], v, S);

            const float P = __shfl_up_sync(0xFFFFFFFFu, S, 1);
            const float Mprev = (lane == 0) ? carry[c]
                                            : fmaf(a4lane[c], carry[c], P);
            const float S31 = __shfl_sync(0xFFFFFFFFu, S, 31);
            const float a128 = (a64[c] * a64[c]);          // recomputed (reg save)
            carry[c] = fmaf(a128, carry[c], S31);

            // fold prefix: m_j = l_j + a^{j+1} * Mprev
            const float a3 = a1[c] * a2[c];                // recomputed (reg save)
            const float m0 = fmaf(a1[c], Mprev, l0);
            const float m1 = fmaf(a2[c], Mprev, l1);
            const float m2 = fmaf(a3,    Mprev, l2);
            const float m3 = fmaf(a4[c], Mprev, l3);

            float4 o;
            {
                const float sm = fast_ex2(-alpha * fast_lg2(PCEN_EPS + m0));
                o.x = poly_ex2(r * fast_lg2(fmaf(xv.x, sm, delta))) - delta_r;
            }
            {
                const float sm = fast_ex2(-alpha * fast_lg2(PCEN_EPS + m1));
                o.y = poly_ex2(r * fast_lg2(fmaf(xv.y, sm, delta))) - delta_r;
            }
            {
                const float sm = fast_ex2(-alpha * fast_lg2(PCEN_EPS + m2));
                o.z = poly_ex2(r * fast_lg2(fmaf(xv.z, sm, delta))) - delta_r;
            }
            {
                const float sm = fast_ex2(-alpha * fast_lg2(PCEN_EPS + m3));
                o.w = poly_ex2(r * fast_lg2(fmaf(xv.w, sm, delta))) - delta_r;
            }
            *(float4*)(op + (size_t)c * s_stride + (size_t)ch * CHUNK + lane * RPT) = o;
        }
    }
}

extern "C" void kernel_launch(void* const* d_in, const int* in_sizes, int n_in,
                              void* d_out, int out_size)
{
    const float* x         = (const float*)d_in[0];
    const float* s_log     = (const float*)d_in[1];
    const float* alpha_log = (const float*)d_in[2];
    const float* delta_log = (const float*)d_in[3];
    const float* r_log     = (const float*)d_in[4];
    float* out = (float*)d_out;

    const int F  = in_sizes[2];
    const int BF = in_sizes[0] / TT;

    const int total_warps = BF * NPAIR;
    const int threads = 128;
    const int warps_per_block = threads / 32;
    const int blocks = (total_warps + warps_per_block - 1) / warps_per_block;

    pcen_kernel<<<blocks, threads>>>(x, s_log, alpha_log, delta_log, r_log,
                                     out, F, BF);
}

// round 8
// speedup vs baseline: 1.1886x; 1.1886x over previous
#include <cuda_runtime.h>
#include <cuda_bf16.h>
#include <cstdint>

// PCEN, 10 smoother coefficients.
//   m[s,t] = (1-s)*m[s,t-1] + s*x[t],  m[s,0] = x[0]
//   out = (x*(EPS+m)^(-alpha) + delta)^r - delta^r
//
// R8: RPT=8 (8 consecutive t per lane, 256-t chunks) halves scan/SHFL
// overhead per element; 3 MUFU + 1 poly-ex2 lowers the XU floor. Both the
// MUFU floor (~53K cyc) and issue floor (~49K cyc) now sit well under R4's
// 71K-cycle MUFU bound. CPW=2 chains per warp, natural register allocation.

#define PCEN_EPS 1e-5f
#define NS 10
#define CPW 2
#define NPAIR (NS / CPW)
#define TT 2048
#define RPT 8
#define CHUNK (32 * RPT)          // 256
#define NCHUNK (TT / CHUNK)       // 8

__device__ __forceinline__ float fast_ex2(float v) {
    float r; asm("ex2.approx.ftz.f32 %0, %1;" : "=f"(r) : "f"(v)); return r;
}
__device__ __forceinline__ float fast_lg2(float v) {
    float r; asm("lg2.approx.ftz.f32 %0, %1;" : "=f"(r) : "f"(v)); return r;
}

// 2^v on FMA/ALU pipes (no MUFU). Valid for |v| < ~126.
__device__ __forceinline__ float poly_ex2(float v) {
    const float magic = 12582912.0f;           // 1.5 * 2^23
    float fl = v + magic;                      // RN -> integer in low mantissa
    int   iv = __float_as_int(fl);
    float t  = v - (fl - magic);               // t in [-0.5, 0.5]
    float u  = t * 0.6931471805599453f;
    float p  = fmaf(u, 8.3333333e-3f, 4.1666667e-2f);
    p = fmaf(p, u, 0.16666667f);
    p = fmaf(p, u, 0.5f);
    p = fmaf(p, u, 1.0f);
    p = fmaf(p, u, 1.0f);
    return __int_as_float(__float_as_int(p) + (iv << 23));
}

__device__ __forceinline__ float pcen_elem(float xv, float m,
                                           float alpha, float delta,
                                           float r, float delta_r) {
    const float sm = fast_ex2(-alpha * fast_lg2(PCEN_EPS + m));
    return poly_ex2(r * fast_lg2(fmaf(xv, sm, delta))) - delta_r;
}

__global__ __launch_bounds__(128) void pcen_kernel(
    const float* __restrict__ x,
    const float* __restrict__ s_log,
    const float* __restrict__ alpha_log,
    const float* __restrict__ delta_log,
    const float* __restrict__ r_log,
    float* __restrict__ out,
    int F, int BF)
{
    const int gwarp = (blockIdx.x * blockDim.x + threadIdx.x) >> 5;
    const int lane  = threadIdx.x & 31;
    if (gwarp >= BF * NPAIR) return;

    const int row  = gwarp / NPAIR;
    const int pair = gwarp % NPAIR;
    const int i0   = pair * CPW;

    const int b = row / F;
    const int f = row % F;

    const float alpha = __expf(alpha_log[f]);
    const float delta = __expf(delta_log[f]);
    const float r     = __expf(r_log[f]);
    const float delta_r = fast_ex2(r * fast_lg2(delta));

    const float4* __restrict__ xp4 = (const float4*)(x + (size_t)row * TT);
    float* __restrict__ op = out + (((size_t)b * NS + i0) * F + f) * (size_t)TT;
    const size_t s_stride = (size_t)F * TT;

    // persistent per-chain state: 11 regs per chain
    float sv[CPW], a1[CPW], a2[CPW], a4[CPW], a8[CPW];
    float a16[CPW], a32[CPW], a64[CPW], a128[CPW];
    float a8lane[CPW], carry[CPW];

    const float x0 = ((const float*)xp4)[0];

    #pragma unroll
    for (int c = 0; c < CPW; c++) {
        const float s = __expf(s_log[i0 + c]);
        sv[c] = s;
        const float a = 1.0f - s;
        a1[c]   = a;
        a2[c]   = a * a;
        a4[c]   = a2[c] * a2[c];
        a8[c]   = a4[c] * a4[c];
        a16[c]  = a8[c] * a8[c];
        a32[c]  = a16[c] * a16[c];
        a64[c]  = a32[c] * a32[c];
        a128[c] = a64[c] * a64[c];
        float ap = 1.0f;                        // (a^8)^lane
        if (lane & 1)  ap *= a8[c];
        if (lane & 2)  ap *= a16[c];
        if (lane & 4)  ap *= a32[c];
        if (lane & 8)  ap *= a64[c];
        if (lane & 16) ap *= a128[c];
        a8lane[c] = ap;
        carry[c] = x0;   // m_{-1} = x0 -> m_0 = x0 (reference init)
    }

    for (int ch = 0; ch < NCHUNK; ch++) {
        // lane owns t in [ch*256 + lane*8, +8): two float4 loads
        const int base4 = ch * 64 + lane * 2;
        const float4 xa = xp4[base4];
        const float4 xb = xp4[base4 + 1];

        #pragma unroll
        for (int c = 0; c < CPW; c++) {
            const float s = sv[c];
            const float a = a1[c];
            // local serial IIR (zero init), 8 steps
            float l0 = s * xa.x;
            float l1 = fmaf(a, l0, s * xa.y);
            float l2 = fmaf(a, l1, s * xa.z);
            float l3 = fmaf(a, l2, s * xa.w);
            float l4 = fmaf(a, l3, s * xb.x);
            float l5 = fmaf(a, l4, s * xb.y);
            float l6 = fmaf(a, l5, s * xb.z);
            float l7 = fmaf(a, l6, s * xb.w);

            // Kogge-Stone over lane aggregates (ratio a^8)
            float S = l7;
            float v;
            v = __shfl_up_sync(0xFFFFFFFFu, S, 1);  if (lane >= 1)  S = fmaf(a8[c],   v, S);
            v = __shfl_up_sync(0xFFFFFFFFu, S, 2);  if (lane >= 2)  S = fmaf(a16[c],  v, S);
            v = __shfl_up_sync(0xFFFFFFFFu, S, 4);  if (lane >= 4)  S = fmaf(a32[c],  v, S);
            v = __shfl_up_sync(0xFFFFFFFFu, S, 8);  if (lane >= 8)  S = fmaf(a64[c],  v, S);
            v = __shfl_up_sync(0xFFFFFFFFu, S, 16); if (lane >= 16) S = fmaf(a128[c], v, S);

            const float P = __shfl_up_sync(0xFFFFFFFFu, S, 1);
            const float Mprev = (lane == 0) ? carry[c]
                                            : fmaf(a8lane[c], carry[c], P);
            const float S31 = __shfl_sync(0xFFFFFFFFu, S, 31);
            const float a256 = a128[c] * a128[c];
            carry[c] = fmaf(a256, carry[c], S31);

            // fold prefix: m_j = l_j + a^{j+1} * Mprev  (a^3,5,6,7 recomputed)
            const float a3 = a1[c] * a2[c];
            const float a5 = a1[c] * a4[c];
            const float a6 = a2[c] * a4[c];
            const float a7 = a3 * a4[c];
            const float m0 = fmaf(a1[c], Mprev, l0);
            const float m1 = fmaf(a2[c], Mprev, l1);
            const float m2 = fmaf(a3,    Mprev, l2);
            const float m3 = fmaf(a4[c], Mprev, l3);
            const float m4 = fmaf(a5,    Mprev, l4);
            const float m5 = fmaf(a6,    Mprev, l5);
            const float m6 = fmaf(a7,    Mprev, l6);
            const float m7 = fmaf(a8[c], Mprev, l7);

            float4 oa, ob;
            oa.x = pcen_elem(xa.x, m0, alpha, delta, r, delta_r);
            oa.y = pcen_elem(xa.y, m1, alpha, delta, r, delta_r);
            oa.z = pcen_elem(xa.z, m2, alpha, delta, r, delta_r);
            oa.w = pcen_elem(xa.w, m3, alpha, delta, r, delta_r);
            ob.x = pcen_elem(xb.x, m4, alpha, delta, r, delta_r);
            ob.y = pcen_elem(xb.y, m5, alpha, delta, r, delta_r);
            ob.z = pcen_elem(xb.z, m6, alpha, delta, r, delta_r);
            ob.w = pcen_elem(xb.w, m7, alpha, delta, r, delta_r);

            float* o = op + (size_t)c * s_stride + (size_t)ch * CHUNK + lane * RPT;
            *(float4*)o       = oa;
            *(float4*)(o + 4) = ob;
        }
    }
}

extern "C" void kernel_launch(void* const* d_in, const int* in_sizes, int n_in,
                              void* d_out, int out_size)
{
    const float* x         = (const float*)d_in[0];
    const float* s_log     = (const float*)d_in[1];
    const float* alpha_log = (const float*)d_in[2];
    const float* delta_log = (const float*)d_in[3];
    const float* r_log     = (const float*)d_in[4];
    float* out = (float*)d_out;

    const int F  = in_sizes[2];
    const int BF = in_sizes[0] / TT;

    const int total_warps = BF * NPAIR;
    const int threads = 128;
    const int warps_per_block = threads / 32;
    const int blocks = (total_warps + warps_per_block - 1) / warps_per_block;

    pcen_kernel<<<blocks, threads>>>(x, s_log, alpha_log, delta_log, r_log,
                                     out, F, BF);
}